// round 1
// baseline (speedup 1.0000x reference)
#include <cuda_runtime.h>

#define NW 6
#define NL 4
#define HP 112
#define WP 112
#define NB 8
#define OC 16
#define NPIX (NB*HP*WP)
#define NOUT (NB*OC*224*224)

__device__ float g_T[6*27];
__device__ float g_y[NB*OC*HP*WP];

// ---------------------------------------------------------------------------
// Kernel 0: circuit precompute. Simulate the 4-layer circuit for the 8 basis
// states of the (wire0,wire1,wire2) subspace (wires 3-5 start at |0>), build
// M_w = Phi^dag Z_w Phi, fold (-i)^popcount phases -> real symmetric M',
// transform half-angle products to the {1, cos a, sin a} basis -> T[6][27].
// ---------------------------------------------------------------------------
__global__ void k_precompute(const float* __restrict__ w)
{
    __shared__ float2 phi[8][64];
    __shared__ float Mre[6][8][8];
    __shared__ float Mim[6][8][8];
    const int tid = threadIdx.x;

    if (tid < 8) {
        const int j = tid;
        float2 st[64];
        #pragma unroll
        for (int s = 0; s < 64; s++) st[s] = make_float2(0.f, 0.f);
        st[j * 8] = make_float2(1.f, 0.f);

        for (int l = 0; l < NL; l++) {
            // single-qubit rotations
            for (int q = 0; q < NW; q++) {
                const float ph = w[(l*NW + q)*3 + 0];
                const float th = w[(l*NW + q)*3 + 1];
                const float om = w[(l*NW + q)*3 + 2];
                const float ch = cosf(0.5f * th), sh = sinf(0.5f * th);
                float cp, sp, cm, sm;
                sincosf(-0.5f * (ph + om), &sp, &cp);  // ep = cp + i sp
                sincosf(-0.5f * (ph - om), &sm, &cm);  // em = cm + i sm
                // U = [[ep*c, -conj(em)*s], [em*s, conj(ep)*c]]
                const float2 u00 = make_float2( cp*ch,  sp*ch);
                const float2 u01 = make_float2(-cm*sh,  sm*sh);
                const float2 u10 = make_float2( cm*sh,  sm*sh);
                const float2 u11 = make_float2( cp*ch, -sp*ch);
                const int stride = 1 << (5 - q);
                for (int s = 0; s < 64; s++) {
                    if (s & stride) continue;
                    const float2 a0 = st[s], a1 = st[s | stride];
                    st[s] = make_float2(
                        u00.x*a0.x - u00.y*a0.y + u01.x*a1.x - u01.y*a1.y,
                        u00.x*a0.y + u00.y*a0.x + u01.x*a1.y + u01.y*a1.x);
                    st[s | stride] = make_float2(
                        u10.x*a0.x - u10.y*a0.y + u11.x*a1.x - u11.y*a1.y,
                        u10.x*a0.y + u10.y*a0.x + u11.x*a1.y + u11.y*a1.x);
                }
            }
            // CNOT ring
            const int r = l % (NW - 1) + 1;
            for (int q = 0; q < NW; q++) {
                const int cb = 1 << (5 - q);
                const int tb = 1 << (5 - ((q + r) % NW));
                for (int s = 0; s < 64; s++) {
                    if ((s & cb) && !(s & tb)) {
                        const float2 tmp = st[s];
                        st[s] = st[s | tb];
                        st[s | tb] = tmp;
                    }
                }
            }
        }
        for (int s = 0; s < 64; s++) phi[j][s] = st[s];
    }
    __syncthreads();

    // M_w[i][j] = sum_s z_w(s) * conj(phi_i[s]) * phi_j[s]
    for (int e = tid; e < 6 * 64; e += blockDim.x) {
        const int q = e / 64, ij = e % 64, i = ij / 8, jj = ij % 8;
        float re = 0.f, im = 0.f;
        for (int s = 0; s < 64; s++) {
            const float z = ((s >> (5 - q)) & 1) ? -1.f : 1.f;
            const float2 a = phi[i][s], b = phi[jj][s];
            re += z * (a.x * b.x + a.y * b.y);
            im += z * (a.x * b.y - a.y * b.x);
        }
        Mre[q][i][jj] = re;
        Mim[q][i][jj] = im;
    }
    __syncthreads();

    // T[q][t0][t1][t2]: half-angle pair products -> {1, cos a, sin a} basis.
    // pair (0,0): (0.5, 0.5, 0); (1,1): (0.5,-0.5,0); (0,1)/(1,0): (0,0,0.5)
    if (tid < 6 * 27) {
        const int q = tid / 27, term = tid % 27;
        const int tt[3] = { term / 9, (term / 3) % 3, term % 3 };
        float acc = 0.f;
        for (int i = 0; i < 8; i++) {
            for (int jj = 0; jj < 8; jj++) {
                const int k = (__popc(i) - __popc(jj)) & 3;  // i^k phase
                const float mre = Mre[q][i][jj], mim = Mim[q][i][jj];
                float f = (k == 0) ? mre : (k == 1) ? -mim : (k == 2) ? -mre : mim;
                #pragma unroll
                for (int c = 0; c < 3; c++) {
                    const int bi = (i >> (2 - c)) & 1;
                    const int bj = (jj >> (2 - c)) & 1;
                    const int t = tt[c];
                    float pc;
                    if (bi == bj)
                        pc = (t == 0) ? 0.5f : (t == 1) ? (bi ? -0.5f : 0.5f) : 0.f;
                    else
                        pc = (t == 2) ? 0.5f : 0.f;
                    f *= pc;
                }
                acc += f;
            }
        }
        g_T[tid] = acc;
    }
}

// ---------------------------------------------------------------------------
// Kernel 1: per patch-pixel: 2x2 mean -> angles -> trig basis -> 6 exps via T
// -> FC(6->16) -> LayerNorm -> ReLU -> y (NCHW scratch).
// ---------------------------------------------------------------------------
__global__ void k_pixels(const float* __restrict__ x,
                         const float* __restrict__ fcw,
                         const float* __restrict__ fcb,
                         const float* __restrict__ lng,
                         const float* __restrict__ lnb)
{
    __shared__ float sT[162], sFC[96], sFB[16], sG[16], sB[16];
    const int tid = threadIdx.x;
    if (tid < 162) sT[tid] = g_T[tid];
    if (tid < 96)  sFC[tid] = fcw[tid];
    if (tid >= 96  && tid < 112) sFB[tid - 96]  = fcb[tid - 96];
    if (tid >= 112 && tid < 128) sG [tid - 112] = lng[tid - 112];
    if (tid >= 128 && tid < 144) sB [tid - 128] = lnb[tid - 128];
    __syncthreads();

    const int pix = blockIdx.x * blockDim.x + tid;
    if (pix >= NPIX) return;
    const int b   = pix / (HP * WP);
    const int rem = pix % (HP * WP);
    const int hp  = rem / WP, wp = rem % WP;

    float g[3][3];
    #pragma unroll
    for (int c = 0; c < 3; c++) {
        const float* base = x + (((long)(b * 3 + c) * 224 + 2 * hp) * 224 + 2 * wp);
        const float2 r0 = *reinterpret_cast<const float2*>(base);
        const float2 r1 = *reinterpret_cast<const float2*>(base + 224);
        const float a = 0.25f * (r0.x + r0.y + r1.x + r1.y);
        float s, cc;
        sincosf(a, &s, &cc);
        g[c][0] = 1.f; g[c][1] = cc; g[c][2] = s;
    }

    float basis[27];
    #pragma unroll
    for (int t0 = 0; t0 < 3; t0++)
        #pragma unroll
        for (int t1 = 0; t1 < 3; t1++) {
            const float p01 = g[0][t0] * g[1][t1];
            #pragma unroll
            for (int t2 = 0; t2 < 3; t2++)
                basis[(t0 * 3 + t1) * 3 + t2] = p01 * g[2][t2];
        }

    float e[6];
    #pragma unroll
    for (int q = 0; q < 6; q++) {
        float acc = 0.f;
        #pragma unroll
        for (int t = 0; t < 27; t++) acc += sT[q * 27 + t] * basis[t];
        e[q] = acc;
    }

    float y[16];
    float mu = 0.f;
    #pragma unroll
    for (int o = 0; o < OC; o++) {
        float acc = sFB[o];
        #pragma unroll
        for (int q = 0; q < 6; q++) acc += sFC[o * 6 + q] * e[q];
        y[o] = acc;
        mu += acc;
    }
    mu *= (1.f / OC);
    float var = 0.f;
    #pragma unroll
    for (int o = 0; o < OC; o++) { const float d = y[o] - mu; var += d * d; }
    var *= (1.f / OC);
    const float inv = rsqrtf(var + 1e-5f);
    #pragma unroll
    for (int o = 0; o < OC; o++) {
        const float v = fmaxf((y[o] - mu) * inv * sG[o] + sB[o], 0.f);
        g_y[((b * OC + o) * HP + hp) * WP + wp] = v;
    }
}

// ---------------------------------------------------------------------------
// Kernel 2: 2x bilinear upsample, jax half-pixel convention.
// even out idx (2m): 0.25*y[m-1] + 0.75*y[m]   (clamped == edge renorm)
// odd  out idx (2m+1): 0.75*y[m] + 0.25*y[m+1] (clamped)
// ---------------------------------------------------------------------------
__global__ void k_resize(float* __restrict__ out)
{
    const int idx = blockIdx.x * blockDim.x + threadIdx.x;
    if (idx >= NOUT) return;
    const int w  = idx % 224;
    const int h  = (idx / 224) % 224;
    const int bc = idx / (224 * 224);

    const int mh = h >> 1, mw = w >> 1;
    int h0, h1; float wh0;
    if (h & 1) { h0 = mh; h1 = min(mh + 1, HP - 1); wh0 = 0.75f; }
    else       { h0 = max(mh - 1, 0); h1 = mh;      wh0 = 0.25f; }
    int w0, w1; float ww0;
    if (w & 1) { w0 = mw; w1 = min(mw + 1, WP - 1); ww0 = 0.75f; }
    else       { w0 = max(mw - 1, 0); w1 = mw;      ww0 = 0.25f; }

    const float* yb = g_y + (long)bc * HP * WP;
    const float v =
        wh0 * (ww0 * yb[h0 * WP + w0] + (1.f - ww0) * yb[h0 * WP + w1]) +
        (1.f - wh0) * (ww0 * yb[h1 * WP + w0] + (1.f - ww0) * yb[h1 * WP + w1]);
    out[idx] = v;
}

extern "C" void kernel_launch(void* const* d_in, const int* in_sizes, int n_in,
                              void* d_out, int out_size)
{
    const float* x   = (const float*)d_in[0];
    const float* wts = (const float*)d_in[1];
    const float* fcw = (const float*)d_in[2];
    const float* fcb = (const float*)d_in[3];
    const float* lng = (const float*)d_in[4];
    const float* lnb = (const float*)d_in[5];
    float* out = (float*)d_out;

    k_precompute<<<1, 192>>>(wts);
    k_pixels<<<(NPIX + 255) / 256, 256>>>(x, fcw, fcb, lng, lnb);
    k_resize<<<(NOUT + 255) / 256, 256>>>(out);
}

// round 2
// speedup vs baseline: 3.2312x; 3.2312x over previous
#include <cuda_runtime.h>

#define NW 6
#define NL 4
#define HP 112
#define WP 112
#define NB 8
#define OC 16
#define NPIX (NB*HP*WP)

__device__ float g_T[6*27];
__device__ float g_y[NB*OC*HP*WP];

// ---------------------------------------------------------------------------
// Kernel 0 (parallelized): simulate the circuit for the 8 basis states of the
// (wire0..2) subspace with the state in SHARED memory, 512 threads =
// 8 basis-states x 64 amplitudes. Then M_w = Phi^dag Z_w Phi, fold the
// (-i)^popcount phases, and transform to the 27-term {1,cos,sin} basis table.
// ---------------------------------------------------------------------------
__global__ void k_precompute(const float* __restrict__ w)
{
    __shared__ float2 sU[24][4];          // u00,u01,u10,u11 per gate
    __shared__ float2 phi[8][64];
    __shared__ float  Mre[6][8][8];
    __shared__ float  Mim[6][8][8];

    const int tid = threadIdx.x;
    const int j = tid >> 6;               // basis state 0..7
    const int s = tid & 63;               // amplitude index 0..63

    // Phase A: 24 threads build the 24 gate matrices
    if (tid < 24) {
        const float ph = w[tid*3 + 0];
        const float th = w[tid*3 + 1];
        const float om = w[tid*3 + 2];
        const float ch = cosf(0.5f * th), sh = sinf(0.5f * th);
        float cp, sp, cm, sm;
        sincosf(-0.5f * (ph + om), &sp, &cp);   // ep = cp + i sp
        sincosf(-0.5f * (ph - om), &sm, &cm);   // em = cm + i sm
        sU[tid][0] = make_float2( cp*ch,  sp*ch);   // u00 = ep*c
        sU[tid][1] = make_float2(-cm*sh,  sm*sh);   // u01 = -conj(em)*s
        sU[tid][2] = make_float2( cm*sh,  sm*sh);   // u10 = em*s
        sU[tid][3] = make_float2( cp*ch, -sp*ch);   // u11 = conj(ep)*c
    }

    // Phase B: init phi[j] = |j>|000>  (amplitude 1 at s = j*8)
    phi[j][s] = make_float2((s == j * 8) ? 1.f : 0.f, 0.f);
    __syncthreads();

    // Phase C: apply gates, all 512 threads in lockstep
    for (int l = 0; l < NL; l++) {
        for (int q = 0; q < NW; q++) {
            const int stride = 1 << (5 - q);
            const float2 u00 = sU[l*6+q][0], u01 = sU[l*6+q][1];
            const float2 u10 = sU[l*6+q][2], u11 = sU[l*6+q][3];
            if (!(s & stride)) {
                const float2 a0 = phi[j][s], a1 = phi[j][s | stride];
                phi[j][s] = make_float2(
                    u00.x*a0.x - u00.y*a0.y + u01.x*a1.x - u01.y*a1.y,
                    u00.x*a0.y + u00.y*a0.x + u01.x*a1.y + u01.y*a1.x);
                phi[j][s | stride] = make_float2(
                    u10.x*a0.x - u10.y*a0.y + u11.x*a1.x - u11.y*a1.y,
                    u10.x*a0.y + u10.y*a0.x + u11.x*a1.y + u11.y*a1.x);
            }
            __syncthreads();
        }
        const int r = l % (NW - 1) + 1;
        for (int q = 0; q < NW; q++) {
            const int cb = 1 << (5 - q);
            const int tb = 1 << (5 - ((q + r) % NW));
            if ((s & cb) && !(s & tb)) {
                const float2 tmp = phi[j][s];
                phi[j][s] = phi[j][s | tb];
                phi[j][s | tb] = tmp;
            }
            __syncthreads();
        }
    }

    // Phase D: M_w[i][jj] = sum_s z_w(s) conj(phi_i[s]) phi_jj[s]
    for (int e = tid; e < 6 * 64; e += blockDim.x) {
        const int q = e / 64, ij = e % 64, i = ij / 8, jj = ij % 8;
        float re = 0.f, im = 0.f;
        #pragma unroll 8
        for (int t = 0; t < 64; t++) {
            const float z = ((t >> (5 - q)) & 1) ? -1.f : 1.f;
            const float2 a = phi[i][t], b = phi[jj][t];
            re += z * (a.x * b.x + a.y * b.y);
            im += z * (a.x * b.y - a.y * b.x);
        }
        Mre[q][i][jj] = re;
        Mim[q][i][jj] = im;
    }
    __syncthreads();

    // Phase E: half-angle pair products -> {1, cos a, sin a} basis table
    if (tid < 6 * 27) {
        const int q = tid / 27, term = tid % 27;
        const int tt[3] = { term / 9, (term / 3) % 3, term % 3 };
        float acc = 0.f;
        for (int i = 0; i < 8; i++) {
            for (int jj = 0; jj < 8; jj++) {
                const int k = (__popc(i) - __popc(jj)) & 3;
                const float mre = Mre[q][i][jj], mim = Mim[q][i][jj];
                float f = (k == 0) ? mre : (k == 1) ? -mim : (k == 2) ? -mre : mim;
                #pragma unroll
                for (int c = 0; c < 3; c++) {
                    const int bi = (i >> (2 - c)) & 1;
                    const int bj = (jj >> (2 - c)) & 1;
                    const int t = tt[c];
                    float pc;
                    if (bi == bj)
                        pc = (t == 0) ? 0.5f : (t == 1) ? (bi ? -0.5f : 0.5f) : 0.f;
                    else
                        pc = (t == 2) ? 0.5f : 0.f;
                    f *= pc;
                }
                acc += f;
            }
        }
        g_T[tid] = acc;
    }
}

// ---------------------------------------------------------------------------
// Kernel 1: each thread handles TWO adjacent patch pixels (float4 reads,
// float2 writes per channel): 2x2 mean -> trig basis -> 6 exps via T ->
// FC(6->16) -> LayerNorm -> ReLU -> y (NCHW scratch).
// ---------------------------------------------------------------------------
__global__ void k_pixels(const float* __restrict__ x,
                         const float* __restrict__ fcw,
                         const float* __restrict__ fcb,
                         const float* __restrict__ lng,
                         const float* __restrict__ lnb)
{
    __shared__ float sT[162], sFC[96], sFB[16], sG[16], sB[16];
    const int tid = threadIdx.x;
    if (tid < 162) sT[tid] = g_T[tid];
    if (tid < 96)  sFC[tid] = fcw[tid];
    if (tid >= 96  && tid < 112) sFB[tid - 96]  = fcb[tid - 96];
    if (tid >= 112 && tid < 128) sG [tid - 112] = lng[tid - 112];
    if (tid >= 128 && tid < 144) sB [tid - 128] = lnb[tid - 128];
    __syncthreads();

    const int pp = blockIdx.x * blockDim.x + tid;     // pixel-pair index
    if (pp >= NPIX / 2) return;
    const int WPH = WP / 2;
    const int b   = pp / (HP * WPH);
    const int rem = pp % (HP * WPH);
    const int hp  = rem / WPH, wpp = rem % WPH;       // pair covers wp=2*wpp, 2*wpp+1

    float g0[3][3], g1[3][3];
    #pragma unroll
    for (int c = 0; c < 3; c++) {
        const float* base = x + (((long)(b * 3 + c) * 224 + 2 * hp) * 224 + 4 * wpp);
        const float4 r0 = *reinterpret_cast<const float4*>(base);
        const float4 r1 = *reinterpret_cast<const float4*>(base + 224);
        const float a0 = 0.25f * (r0.x + r0.y + r1.x + r1.y);
        const float a1 = 0.25f * (r0.z + r0.w + r1.z + r1.w);
        float sn, cs;
        sincosf(a0, &sn, &cs);
        g0[c][0] = 1.f; g0[c][1] = cs; g0[c][2] = sn;
        sincosf(a1, &sn, &cs);
        g1[c][0] = 1.f; g1[c][1] = cs; g1[c][2] = sn;
    }

    float2 vout[OC];
    #pragma unroll
    for (int half = 0; half < 2; half++) {
        float (*gg)[3] = half ? g1 : g0;

        float e[6];
        #pragma unroll
        for (int q = 0; q < 6; q++) e[q] = 0.f;
        #pragma unroll
        for (int t0 = 0; t0 < 3; t0++)
            #pragma unroll
            for (int t1 = 0; t1 < 3; t1++) {
                const float p01 = gg[0][t0] * gg[1][t1];
                #pragma unroll
                for (int t2 = 0; t2 < 3; t2++) {
                    const float bas = p01 * gg[2][t2];
                    const int t = (t0 * 3 + t1) * 3 + t2;
                    #pragma unroll
                    for (int q = 0; q < 6; q++) e[q] += sT[q * 27 + t] * bas;
                }
            }

        float y[OC], mu = 0.f;
        #pragma unroll
        for (int o = 0; o < OC; o++) {
            float acc = sFB[o];
            #pragma unroll
            for (int q = 0; q < 6; q++) acc += sFC[o * 6 + q] * e[q];
            y[o] = acc;
            mu += acc;
        }
        mu *= (1.f / OC);
        float var = 0.f;
        #pragma unroll
        for (int o = 0; o < OC; o++) { const float d = y[o] - mu; var += d * d; }
        var *= (1.f / OC);
        const float inv = rsqrtf(var + 1e-5f);
        #pragma unroll
        for (int o = 0; o < OC; o++) {
            const float v = fmaxf((y[o] - mu) * inv * sG[o] + sB[o], 0.f);
            if (half) vout[o].y = v; else vout[o].x = v;
        }
    }

    #pragma unroll
    for (int o = 0; o < OC; o++) {
        *reinterpret_cast<float2*>(
            &g_y[(((long)b * OC + o) * HP + hp) * WP + 2 * wpp]) = vout[o];
    }
}

// ---------------------------------------------------------------------------
// Kernel 2: tiled 2x bilinear upsample (jax half-pixel convention).
// Each thread owns one input pixel and produces its 2x2 output quad.
// Shared 18x18 tile (halo 1, clamped) per 16x16 input block.
// ---------------------------------------------------------------------------
__global__ void k_resize(float* __restrict__ out)
{
    __shared__ float t[18][19];
    const int bc = blockIdx.z;
    const int ih0 = blockIdx.y * 16 - 1;
    const int iw0 = blockIdx.x * 16 - 1;
    const float* yb = g_y + (long)bc * HP * WP;

    const int tx = threadIdx.x, ty = threadIdx.y;
    const int lin = ty * 16 + tx;
    for (int i = lin; i < 18 * 18; i += 256) {
        const int r = i / 18, c = i % 18;
        const int gr = min(max(ih0 + r, 0), HP - 1);
        const int gc = min(max(iw0 + c, 0), WP - 1);
        t[r][c] = yb[gr * WP + gc];
    }
    __syncthreads();

    // input pixel (m, n); shared coords row ty+1, col tx+1
    const int r0 = ty, r1 = ty + 1, r2 = ty + 2;
    const int c0 = tx, c1 = tx + 1, c2 = tx + 2;
    // horizontal blends per row: a = even out col, bq = odd out col
    const float a_0 = 0.25f * t[r0][c0] + 0.75f * t[r0][c1];
    const float b_0 = 0.75f * t[r0][c1] + 0.25f * t[r0][c2];
    const float a_1 = 0.25f * t[r1][c0] + 0.75f * t[r1][c1];
    const float b_1 = 0.75f * t[r1][c1] + 0.25f * t[r1][c2];
    const float a_2 = 0.25f * t[r2][c0] + 0.75f * t[r2][c1];
    const float b_2 = 0.75f * t[r2][c1] + 0.25f * t[r2][c2];

    const int oh = 2 * (blockIdx.y * 16 + ty);
    const int ow = 2 * (blockIdx.x * 16 + tx);
    float* obase = out + ((long)bc * 224 + oh) * 224 + ow;
    *reinterpret_cast<float2*>(obase) =
        make_float2(0.25f * a_0 + 0.75f * a_1, 0.25f * b_0 + 0.75f * b_1);
    *reinterpret_cast<float2*>(obase + 224) =
        make_float2(0.75f * a_1 + 0.25f * a_2, 0.75f * b_1 + 0.25f * b_2);
}

extern "C" void kernel_launch(void* const* d_in, const int* in_sizes, int n_in,
                              void* d_out, int out_size)
{
    const float* x   = (const float*)d_in[0];
    const float* wts = (const float*)d_in[1];
    const float* fcw = (const float*)d_in[2];
    const float* fcb = (const float*)d_in[3];
    const float* lng = (const float*)d_in[4];
    const float* lnb = (const float*)d_in[5];
    float* out = (float*)d_out;

    k_precompute<<<1, 512>>>(wts);
    k_pixels<<<(NPIX/2 + 255) / 256, 256>>>(x, fcw, fcb, lng, lnb);
    dim3 rb(16, 16);
    dim3 rg(WP / 16, HP / 16, NB * OC);
    k_resize<<<rg, rb>>>(out);
}